// round 16
// baseline (speedup 1.0000x reference)
#include <cuda_runtime.h>
#include <cuda_bf16.h>
#include <cstdint>

#define N_NODES 100000
#define N_EDGES 800000
#define F 128      // IN_FEATS == N_HIDDEN
#define C 64       // N_CLASSES

// ---------------------------------------------------------------------------
// Scratch (no cudaMalloc allowed)
// ---------------------------------------------------------------------------
__device__ __nv_bfloat16 g_hnh[(size_t)N_NODES * F];   // hn hi, 25.6 MB
__device__ __nv_bfloat16 g_hnl[(size_t)N_NODES * F];   // hn lo, 25.6 MB
__device__ __nv_bfloat16 g_w1h[F * F], g_w1l[F * F];   // W1^T as [N][K]
__device__ __nv_bfloat16 g_w2h[C * F], g_w2l[C * F];   // W2^T as [N][K]
__device__ int g_esrc[N_EDGES];
__device__ int g_deg[N_NODES];
__device__ int g_rowptr[N_NODES];
__device__ int g_cursor[N_NODES];
__device__ int g_total;

// ---------------------------------------------------------------------------
// mma.sync / ldmatrix helpers (portable PTX, OK on compute_103 virtual arch)
// ---------------------------------------------------------------------------
__device__ __forceinline__ uint32_t smem_u32(const void* p) {
    uint32_t a;
    asm("{ .reg .u64 t; cvta.to.shared.u64 t, %1; cvt.u32.u64 %0, t; }"
        : "=r"(a) : "l"(p));
    return a;
}
#define LDSM4(r0, r1, r2, r3, addr) \
    asm volatile("ldmatrix.sync.aligned.m8n8.x4.shared.b16 {%0,%1,%2,%3}, [%4];" \
                 : "=r"(r0), "=r"(r1), "=r"(r2), "=r"(r3) : "r"(addr))
#define MMA16816(c, a, b) \
    asm volatile("mma.sync.aligned.m16n8k16.row.col.f32.bf16.bf16.f32 " \
                 "{%0,%1,%2,%3}, {%4,%5,%6,%7}, {%8,%9}, {%0,%1,%2,%3};" \
                 : "+f"((c)[0]), "+f"((c)[1]), "+f"((c)[2]), "+f"((c)[3]) \
                 : "r"((a)[0]), "r"((a)[1]), "r"((a)[2]), "r"((a)[3]), \
                   "r"((b)[0]), "r"((b)[1]))

__device__ __forceinline__ uint32_t pack_bf16hi(float v0, float v1) {
    __nv_bfloat162 p = __halves2bfloat162(__float2bfloat16(v0), __float2bfloat16(v1));
    return *(uint32_t*)&p;
}
__device__ __forceinline__ uint32_t pack_bf16lo(float v0, float v1) {
    __nv_bfloat16 h0 = __float2bfloat16(v0);
    __nv_bfloat16 h1 = __float2bfloat16(v1);
    __nv_bfloat162 p = __halves2bfloat162(
        __float2bfloat16(v0 - __bfloat162float(h0)),
        __float2bfloat16(v1 - __bfloat162float(h1)));
    return *(uint32_t*)&p;
}

// ---------------------------------------------------------------------------
// K0: fused zero(deg,total) + weight split/transpose   (R8 exact)
// ---------------------------------------------------------------------------
__global__ void k_prep(const float* __restrict__ W1, const float* __restrict__ W2) {
    int i = blockIdx.x * blockDim.x + threadIdx.x;
    if (i == 0) g_total = 0;
    if (i < N_NODES) g_deg[i] = 0;
    if (i < F * F) {
        int k = i / F, n = i % F;
        float v = W1[i];                       // W1[k][n]
        __nv_bfloat16 h = __float2bfloat16(v);
        g_w1h[n * F + k] = h;
        g_w1l[n * F + k] = __float2bfloat16(v - __bfloat162float(h));
    }
    if (i < C * F) {
        int k = i / C, n = i % C;
        float v = W2[i];                       // W2[k][n]
        __nv_bfloat16 h = __float2bfloat16(v);
        g_w2h[n * F + k] = h;
        g_w2l[n * F + k] = __float2bfloat16(v - __bfloat162float(h));
    }
}

// ---------------------------------------------------------------------------
// K1: degree histogram (2 edges/thread, full occupancy)   (R8 exact)
// ---------------------------------------------------------------------------
__global__ void k_hist(const int* __restrict__ dst) {
    int i = (blockIdx.x * blockDim.x + threadIdx.x) * 2;
    if (i < N_EDGES)     atomicAdd(&g_deg[dst[i]], 1);
    if (i + 1 < N_EDGES) atomicAdd(&g_deg[dst[i + 1]], 1);
}

// ---------------------------------------------------------------------------
// K2: UNORDERED CSR allocation (warp scan + one atomic/warp)   (R8 exact)
// ---------------------------------------------------------------------------
__global__ void __launch_bounds__(256) k_alloc() {
    int v = blockIdx.x * blockDim.x + threadIdx.x;
    int lane = threadIdx.x & 31;
    int d = (v < N_NODES) ? g_deg[v] : 0;
    int incl = d;
    #pragma unroll
    for (int o = 1; o < 32; o <<= 1) {
        int t = __shfl_up_sync(0xFFFFFFFFu, incl, o);
        if (lane >= o) incl += t;
    }
    int wsum = __shfl_sync(0xFFFFFFFFu, incl, 31);
    int base = 0;
    if (lane == 31) base = atomicAdd(&g_total, wsum);
    base = __shfl_sync(0xFFFFFFFFu, base, 31);
    if (v < N_NODES) {
        int r = base + incl - d;
        g_rowptr[v] = r;
        g_cursor[v] = r;
    }
}

// ---------------------------------------------------------------------------
// K3: scatter edges into per-dst segments (2 edges/thread)   (R8 exact)
// ---------------------------------------------------------------------------
__global__ void k_fill(const int* __restrict__ src, const int* __restrict__ dst) {
    int i = (blockIdx.x * blockDim.x + threadIdx.x) * 2;
    if (i < N_EDGES) {
        int pos = atomicAdd(&g_cursor[dst[i]], 1);
        g_esrc[pos] = src[i];
    }
    if (i + 1 < N_EDGES) {
        int pos = atomicAdd(&g_cursor[dst[i + 1]], 1);
        g_esrc[pos] = src[i + 1];
    }
}

// ---------------------------------------------------------------------------
// K4: gather-sum per node (fp32 x). One warp/node, lane owns one float4. (R8)
// ---------------------------------------------------------------------------
__global__ void __launch_bounds__(256) k_gather(const float* __restrict__ x) {
    int warp = (blockIdx.x * blockDim.x + threadIdx.x) >> 5;
    int lane = threadIdx.x & 31;
    if (warp >= N_NODES) return;
    const int v = warp;
    const float4* x4 = (const float4*)x;

    float4 acc = x4[(size_t)v * 32 + lane];        // self term
    const int start = g_rowptr[v];
    const int deg   = g_deg[v];
    const int end   = start + deg;

    int j = start;
    for (; j + 3 < end; j += 4) {                  // MLP = 4
        int s0 = __ldg(&g_esrc[j]);
        int s1 = __ldg(&g_esrc[j + 1]);
        int s2 = __ldg(&g_esrc[j + 2]);
        int s3 = __ldg(&g_esrc[j + 3]);
        float4 a = x4[(size_t)s0 * 32 + lane];
        float4 b = x4[(size_t)s1 * 32 + lane];
        float4 c = x4[(size_t)s2 * 32 + lane];
        float4 d = x4[(size_t)s3 * 32 + lane];
        acc.x += (a.x + b.x) + (c.x + d.x);
        acc.y += (a.y + b.y) + (c.y + d.y);
        acc.z += (a.z + b.z) + (c.z + d.z);
        acc.w += (a.w + b.w) + (c.w + d.w);
    }
    for (; j < end; j++) {
        int s0 = __ldg(&g_esrc[j]);
        float4 a = x4[(size_t)s0 * 32 + lane];
        acc.x += a.x; acc.y += a.y; acc.z += a.z; acc.w += a.w;
    }

    float inv = 1.0f / (float)(deg + 1);
    acc.x *= inv; acc.y *= inv; acc.z *= inv; acc.w *= inv;

    uint2 hv, lv;
    hv.x = pack_bf16hi(acc.x, acc.y); hv.y = pack_bf16hi(acc.z, acc.w);
    lv.x = pack_bf16lo(acc.x, acc.y); lv.y = pack_bf16lo(acc.z, acc.w);
    ((uint2*)g_hnh)[(size_t)v * 32 + lane] = hv;
    ((uint2*)g_hnl)[(size_t)v * 32 + lane] = lv;
}

// ---------------------------------------------------------------------------
// K5: PERSISTENT GEMM, 256 thr / 8 warps, warp tile 32x64.
// GEMM2 consumes GEMM1 accumulators DIRECTLY as register A-fragments
// (flash-attn P->A mapping); each warp computes a k-partial of out[32x64]
// over its 64 E-columns, then the two wn halves reduce through smem.
// ---------------------------------------------------------------------------
#define RS 136                              // row stride in bf16
#define RSB (RS * 2)                        // row stride in bytes (272)
#define SM_BIAS  0                          // 192 floats
#define SM_AH    1024
#define SM_AL    (SM_AH  + 128 * RSB)
#define SM_W1H   (SM_AL  + 128 * RSB)
#define SM_W1L   (SM_W1H + 128 * RSB)
#define SM_W2H   (SM_W1L + 128 * RSB)
#define SM_W2L   (SM_W2H + 64 * RSB)
#define SMEM_MM  (SM_W2L + 64 * RSB)        // 175,872 B

// partial-sum region reuses SM_AH after GEMM1: 4 m-groups x 32 rows x 272 B
#define PRSB 272                            // 68 floats/row, conflict-free
#define SM_PART SM_AH

#define N_TILES ((N_NODES + 127) / 128)     // 782
#define GEMM_GRID 148

__global__ void __launch_bounds__(256) k_gemm_mma(
    const float* __restrict__ b1, const float* __restrict__ b2,
    float* __restrict__ out, float* __restrict__ emb)
{
    extern __shared__ char smem[];
    const uint32_t sb = smem_u32(smem);
    const int tid  = threadIdx.x;
    const int wid  = tid >> 5;
    const int lane = tid & 31;

    float* sBias = (float*)(smem + SM_BIAS);

    // --- stage bias + weights ONCE ---
    if (tid < F) sBias[tid] = b1[tid];
    else if (tid < F + C) sBias[tid] = b2[tid - F];
    {
        const uint4* w1h4 = (const uint4*)g_w1h;
        const uint4* w1l4 = (const uint4*)g_w1l;
        #pragma unroll
        for (int i = tid; i < 128 * 16; i += 256) {
            int r = i >> 4, c = i & 15;
            *(uint4*)(smem + SM_W1H + r * RSB + c * 16) = w1h4[i];
            *(uint4*)(smem + SM_W1L + r * RSB + c * 16) = w1l4[i];
        }
        const uint4* w2h4 = (const uint4*)g_w2h;
        const uint4* w2l4 = (const uint4*)g_w2l;
        #pragma unroll
        for (int i = tid; i < 64 * 16; i += 256) {
            int r = i >> 4, c = i & 15;
            *(uint4*)(smem + SM_W2H + r * RSB + c * 16) = w2h4[i];
            *(uint4*)(smem + SM_W2L + r * RSB + c * 16) = w2l4[i];
        }
    }

    // ldmatrix per-lane address components
    const int g  = lane >> 3, lr = lane & 7;
    const int a_row = lr + ((g & 1) << 3);
    const int a_kof = (g >> 1) << 3;
    const int b_row = lr + ((g >> 1) << 3);
    const int b_kof = (g & 1) << 3;
    const int wm = wid & 3;                       // M quarter: rows [wm*32,+32)
    const int wn = wid >> 2;                      // E-col half: [wn*64,+64)

    const int qr = lane >> 2;                     // 0..7
    const int qc = (lane & 3) * 2;                // 0,2,4,6

    for (int tile = blockIdx.x; tile < N_TILES; tile += GEMM_GRID) {
        const int node0 = tile * 128;
        __syncthreads();   // prev partial reads + prev A reads complete

        // --- stage A (hn hi/lo) ---
        #pragma unroll
        for (int i = tid; i < 128 * 16; i += 256) {
            int r = i >> 4, c = i & 15;
            int node = node0 + r;
            uint4 vh = make_uint4(0, 0, 0, 0), vl = make_uint4(0, 0, 0, 0);
            if (node < N_NODES) {
                vh = ((const uint4*)g_hnh)[(size_t)node * 16 + c];
                vl = ((const uint4*)g_hnl)[(size_t)node * 16 + c];
            }
            *(uint4*)(smem + SM_AH + r * RSB + c * 16) = vh;
            *(uint4*)(smem + SM_AL + r * RSB + c * 16) = vl;
        }
        __syncthreads();

        // ================= GEMM1: [128 x 128], warp 32x64 ==================
        float acc[2][8][4];
        #pragma unroll
        for (int m = 0; m < 2; m++)
            #pragma unroll
            for (int n = 0; n < 8; n++)
                #pragma unroll
                for (int q = 0; q < 4; q++) acc[m][n][q] = 0.f;

        #pragma unroll
        for (int ks = 0; ks < 8; ks++) {
            const int k0 = ks * 16;
            uint32_t ah[2][4], al[2][4];
            #pragma unroll
            for (int m = 0; m < 2; m++) {
                int row = wm * 32 + m * 16 + a_row;
                uint32_t off = row * RSB + (k0 + a_kof) * 2;
                LDSM4(ah[m][0], ah[m][1], ah[m][2], ah[m][3], sb + SM_AH + off);
                LDSM4(al[m][0], al[m][1], al[m][2], al[m][3], sb + SM_AL + off);
            }
            uint32_t bh[8][2], bl[8][2];
            #pragma unroll
            for (int nn = 0; nn < 4; nn++) {
                int row = wn * 64 + nn * 16 + b_row;
                uint32_t off = row * RSB + (k0 + b_kof) * 2;
                LDSM4(bh[2*nn][0], bh[2*nn][1], bh[2*nn+1][0], bh[2*nn+1][1],
                      sb + SM_W1H + off);
                LDSM4(bl[2*nn][0], bl[2*nn][1], bl[2*nn+1][0], bl[2*nn+1][1],
                      sb + SM_W1L + off);
            }
            #pragma unroll
            for (int m = 0; m < 2; m++)
                #pragma unroll
                for (int n = 0; n < 8; n++) {
                    MMA16816(acc[m][n], ah[m], bh[n]);
                    MMA16816(acc[m][n], ah[m], bl[n]);
                    MMA16816(acc[m][n], al[m], bh[n]);
                }
        }
        __syncthreads();   // A reads done; SM_AH now reusable for partials

        // --- epilogue1: +b1, relu -> emb; build GEMM2 A-fragments in REGS ---
        // C(m16n8) -> A(m16k16): a0=pack(c0,c1 of n-tile 2j), a1=pack(c2,c3),
        // a2/a3 same from n-tile 2j+1. Warp's E-cols [wn*64,+64) = its k-range.
        uint32_t Eh[2][4][4], El[2][4][4];
        #pragma unroll
        for (int m = 0; m < 2; m++) {
            #pragma unroll
            for (int n = 0; n < 8; n++) {
                int col = wn * 64 + n * 8 + qc;
                float bA = sBias[col], bB = sBias[col + 1];
                float v0 = fmaxf(acc[m][n][0] + bA, 0.f);   // row qr
                float v1 = fmaxf(acc[m][n][1] + bB, 0.f);
                float v2 = fmaxf(acc[m][n][2] + bA, 0.f);   // row qr+8
                float v3 = fmaxf(acc[m][n][3] + bB, 0.f);
                int node = node0 + wm * 32 + m * 16 + qr;
                if (node < N_NODES)
                    *(float2*)(emb + (size_t)node * F + col) = make_float2(v0, v1);
                if (node + 8 < N_NODES)
                    *(float2*)(emb + (size_t)(node + 8) * F + col) = make_float2(v2, v3);
                int j = n >> 1, h = n & 1;                  // kfrag j, half h
                Eh[m][j][h * 2 + 0] = pack_bf16hi(v0, v1);
                Eh[m][j][h * 2 + 1] = pack_bf16hi(v2, v3);
                El[m][j][h * 2 + 0] = pack_bf16lo(v0, v1);
                El[m][j][h * 2 + 1] = pack_bf16lo(v2, v3);
            }
        }

        // ================= GEMM2 partial: out[32 x 64] over k=[wn*64,+64) ===
        float acc2[2][8][4];
        #pragma unroll
        for (int m = 0; m < 2; m++)
            #pragma unroll
            for (int n = 0; n < 8; n++)
                #pragma unroll
                for (int q = 0; q < 4; q++) acc2[m][n][q] = 0.f;

        #pragma unroll
        for (int j = 0; j < 4; j++) {                 // kfrag within warp range
            const int k0 = wn * 64 + j * 16;
            uint32_t bh[8][2], bl[8][2];
            #pragma unroll
            for (int nn = 0; nn < 4; nn++) {
                int row = nn * 16 + b_row;            // all 64 W2 rows
                uint32_t off = row * RSB + (k0 + b_kof) * 2;
                LDSM4(bh[2*nn][0], bh[2*nn][1], bh[2*nn+1][0], bh[2*nn+1][1],
                      sb + SM_W2H + off);
                LDSM4(bl[2*nn][0], bl[2*nn][1], bl[2*nn+1][0], bl[2*nn+1][1],
                      sb + SM_W2L + off);
            }
            #pragma unroll
            for (int m = 0; m < 2; m++)
                #pragma unroll
                for (int n = 0; n < 8; n++) {
                    MMA16816(acc2[m][n], Eh[m][j], bh[n]);
                    MMA16816(acc2[m][n], Eh[m][j], bl[n]);
                    MMA16816(acc2[m][n], El[m][j], bh[n]);
                }
        }

        // --- cross-warp k-reduction: wn=1 stores partials, wn=0 adds ---
        if (wn == 1) {
            char* part = smem + SM_PART + wm * (32 * PRSB);
            #pragma unroll
            for (int m = 0; m < 2; m++)
                #pragma unroll
                for (int n = 0; n < 8; n++) {
                    int r0 = m * 16 + qr, col = n * 8 + qc;
                    *(float2*)(part + r0 * PRSB + col * 4) =
                        make_float2(acc2[m][n][0], acc2[m][n][1]);
                    *(float2*)(part + (r0 + 8) * PRSB + col * 4) =
                        make_float2(acc2[m][n][2], acc2[m][n][3]);
                }
        }
        __syncthreads();
        if (wn == 0) {
            const char* part = smem + SM_PART + wm * (32 * PRSB);
            #pragma unroll
            for (int m = 0; m < 2; m++)
                #pragma unroll
                for (int n = 0; n < 8; n++) {
                    int r0 = m * 16 + qr, col = n * 8 + qc;
                    float bA = sBias[F + col], bB = sBias[F + col + 1];
                    float2 p0 = *(const float2*)(part + r0 * PRSB + col * 4);
                    float2 p1 = *(const float2*)(part + (r0 + 8) * PRSB + col * 4);
                    int node = node0 + wm * 32 + r0;
                    if (node < N_NODES)
                        *(float2*)(out + (size_t)node * C + col) =
                            make_float2(acc2[m][n][0] + p0.x + bA,
                                        acc2[m][n][1] + p0.y + bB);
                    if (node + 8 < N_NODES)
                        *(float2*)(out + (size_t)(node + 8) * C + col) =
                            make_float2(acc2[m][n][2] + p1.x + bA,
                                        acc2[m][n][3] + p1.y + bB);
                }
        }
    }
}

// ---------------------------------------------------------------------------
extern "C" void kernel_launch(void* const* d_in, const int* in_sizes, int n_in,
                              void* d_out, int out_size) {
    const float* x   = (const float*)d_in[0];
    const int*   src = (const int*)d_in[1];
    const int*   dst = (const int*)d_in[2];
    const float* W1  = (const float*)d_in[3];
    const float* b1  = (const float*)d_in[4];
    const float* W2  = (const float*)d_in[5];
    const float* b2  = (const float*)d_in[6];

    float* out = (float*)d_out;                       // [N_NODES, 64]
    float* emb = out + (size_t)N_NODES * C;           // [N_NODES, 128]

    // prep: zero counters + weight split
    k_prep<<<(N_NODES + 255) / 256, 256>>>(W1, W2);
    // CSR build (unordered segments)
    k_hist<<<(N_EDGES / 2 + 255) / 256, 256>>>(dst);
    k_alloc<<<(N_NODES + 255) / 256, 256>>>();
    k_fill<<<(N_EDGES / 2 + 255) / 256, 256>>>(src, dst);
    // gather-sum + normalize + bf16 split
    k_gather<<<(N_NODES * 32 + 255) / 256, 256>>>(x);
    // persistent GEMMs: register-passed GEMM2, cross-warp k-reduction
    cudaFuncSetAttribute(k_gemm_mma, cudaFuncAttributeMaxDynamicSharedMemorySize,
                         SMEM_MM);
    k_gemm_mma<<<GEMM_GRID, 256, SMEM_MM>>>(b1, b2, out, emb);
}

// round 17
// speedup vs baseline: 1.0020x; 1.0020x over previous
#include <cuda_runtime.h>
#include <cuda_bf16.h>
#include <cstdint>

#define N_NODES 100000
#define N_EDGES 800000
#define F 128      // IN_FEATS == N_HIDDEN
#define C 64       // N_CLASSES

// ---------------------------------------------------------------------------
// Scratch (no cudaMalloc allowed)
// ---------------------------------------------------------------------------
__device__ __nv_bfloat16 g_hnh[(size_t)N_NODES * F];   // hn hi, 25.6 MB
__device__ __nv_bfloat16 g_hnl[(size_t)N_NODES * F];   // hn lo, 25.6 MB
__device__ __nv_bfloat16 g_w1h[F * F], g_w1l[F * F];   // W1^T as [N][K]
__device__ __nv_bfloat16 g_w2h[C * F], g_w2l[C * F];   // W2^T as [N][K]
__device__ int g_esrc[N_EDGES];
__device__ int g_deg[N_NODES];
__device__ int g_rowptr[N_NODES];
__device__ int g_cursor[N_NODES];
__device__ int g_total;

// ---------------------------------------------------------------------------
// mma.sync / ldmatrix helpers (portable PTX, OK on compute_103 virtual arch)
// ---------------------------------------------------------------------------
__device__ __forceinline__ uint32_t smem_u32(const void* p) {
    uint32_t a;
    asm("{ .reg .u64 t; cvta.to.shared.u64 t, %1; cvt.u32.u64 %0, t; }"
        : "=r"(a) : "l"(p));
    return a;
}
#define LDSM4(r0, r1, r2, r3, addr) \
    asm volatile("ldmatrix.sync.aligned.m8n8.x4.shared.b16 {%0,%1,%2,%3}, [%4];" \
                 : "=r"(r0), "=r"(r1), "=r"(r2), "=r"(r3) : "r"(addr))
#define MMA16816(c, a, b) \
    asm volatile("mma.sync.aligned.m16n8k16.row.col.f32.bf16.bf16.f32 " \
                 "{%0,%1,%2,%3}, {%4,%5,%6,%7}, {%8,%9}, {%0,%1,%2,%3};" \
                 : "+f"((c)[0]), "+f"((c)[1]), "+f"((c)[2]), "+f"((c)[3]) \
                 : "r"((a)[0]), "r"((a)[1]), "r"((a)[2]), "r"((a)[3]), \
                   "r"((b)[0]), "r"((b)[1]))

// ---------------------------------------------------------------------------
// K0: fused zero(deg,total) + weight split/transpose   (R8 exact)
// ---------------------------------------------------------------------------
__global__ void k_prep(const float* __restrict__ W1, const float* __restrict__ W2) {
    int i = blockIdx.x * blockDim.x + threadIdx.x;
    if (i == 0) g_total = 0;
    if (i < N_NODES) g_deg[i] = 0;
    if (i < F * F) {
        int k = i / F, n = i % F;
        float v = W1[i];                       // W1[k][n]
        __nv_bfloat16 h = __float2bfloat16(v);
        g_w1h[n * F + k] = h;
        g_w1l[n * F + k] = __float2bfloat16(v - __bfloat162float(h));
    }
    if (i < C * F) {
        int k = i / C, n = i % C;
        float v = W2[i];                       // W2[k][n]
        __nv_bfloat16 h = __float2bfloat16(v);
        g_w2h[n * F + k] = h;
        g_w2l[n * F + k] = __float2bfloat16(v - __bfloat162float(h));
    }
}

// ---------------------------------------------------------------------------
// K1: degree histogram (2 edges/thread, full occupancy)   (R8 exact)
// ---------------------------------------------------------------------------
__global__ void k_hist(const int* __restrict__ dst) {
    int i = (blockIdx.x * blockDim.x + threadIdx.x) * 2;
    if (i < N_EDGES)     atomicAdd(&g_deg[dst[i]], 1);
    if (i + 1 < N_EDGES) atomicAdd(&g_deg[dst[i + 1]], 1);
}

// ---------------------------------------------------------------------------
// K2: UNORDERED CSR allocation (warp scan + one atomic/warp)   (R8 exact)
// ---------------------------------------------------------------------------
__global__ void __launch_bounds__(256) k_alloc() {
    int v = blockIdx.x * blockDim.x + threadIdx.x;
    int lane = threadIdx.x & 31;
    int d = (v < N_NODES) ? g_deg[v] : 0;
    int incl = d;
    #pragma unroll
    for (int o = 1; o < 32; o <<= 1) {
        int t = __shfl_up_sync(0xFFFFFFFFu, incl, o);
        if (lane >= o) incl += t;
    }
    int wsum = __shfl_sync(0xFFFFFFFFu, incl, 31);
    int base = 0;
    if (lane == 31) base = atomicAdd(&g_total, wsum);
    base = __shfl_sync(0xFFFFFFFFu, base, 31);
    if (v < N_NODES) {
        int r = base + incl - d;
        g_rowptr[v] = r;
        g_cursor[v] = r;
    }
}

// ---------------------------------------------------------------------------
// K3: scatter edges into per-dst segments (2 edges/thread)   (R8 exact)
// ---------------------------------------------------------------------------
__global__ void k_fill(const int* __restrict__ src, const int* __restrict__ dst) {
    int i = (blockIdx.x * blockDim.x + threadIdx.x) * 2;
    if (i < N_EDGES) {
        int pos = atomicAdd(&g_cursor[dst[i]], 1);
        g_esrc[pos] = src[i];
    }
    if (i + 1 < N_EDGES) {
        int pos = atomicAdd(&g_cursor[dst[i + 1]], 1);
        g_esrc[pos] = src[i + 1];
    }
}

// ---------------------------------------------------------------------------
// K4: gather-sum per node (fp32 x). One warp/node, lane owns one float4. (R8)
// ---------------------------------------------------------------------------
__global__ void __launch_bounds__(256) k_gather(const float* __restrict__ x) {
    int warp = (blockIdx.x * blockDim.x + threadIdx.x) >> 5;
    int lane = threadIdx.x & 31;
    if (warp >= N_NODES) return;
    const int v = warp;
    const float4* x4 = (const float4*)x;

    float4 acc = x4[(size_t)v * 32 + lane];        // self term
    const int start = g_rowptr[v];
    const int deg   = g_deg[v];
    const int end   = start + deg;

    int j = start;
    for (; j + 3 < end; j += 4) {                  // MLP = 4
        int s0 = __ldg(&g_esrc[j]);
        int s1 = __ldg(&g_esrc[j + 1]);
        int s2 = __ldg(&g_esrc[j + 2]);
        int s3 = __ldg(&g_esrc[j + 3]);
        float4 a = x4[(size_t)s0 * 32 + lane];
        float4 b = x4[(size_t)s1 * 32 + lane];
        float4 c = x4[(size_t)s2 * 32 + lane];
        float4 d = x4[(size_t)s3 * 32 + lane];
        acc.x += (a.x + b.x) + (c.x + d.x);
        acc.y += (a.y + b.y) + (c.y + d.y);
        acc.z += (a.z + b.z) + (c.z + d.z);
        acc.w += (a.w + b.w) + (c.w + d.w);
    }
    for (; j < end; j++) {
        int s0 = __ldg(&g_esrc[j]);
        float4 a = x4[(size_t)s0 * 32 + lane];
        acc.x += a.x; acc.y += a.y; acc.z += a.z; acc.w += a.w;
    }

    float inv = 1.0f / (float)(deg + 1);
    acc.x *= inv; acc.y *= inv; acc.z *= inv; acc.w *= inv;

    __nv_bfloat16 h0 = __float2bfloat16(acc.x);
    __nv_bfloat16 h1 = __float2bfloat16(acc.y);
    __nv_bfloat16 h2 = __float2bfloat16(acc.z);
    __nv_bfloat16 h3 = __float2bfloat16(acc.w);
    __nv_bfloat16 l0 = __float2bfloat16(acc.x - __bfloat162float(h0));
    __nv_bfloat16 l1 = __float2bfloat16(acc.y - __bfloat162float(h1));
    __nv_bfloat16 l2 = __float2bfloat16(acc.z - __bfloat162float(h2));
    __nv_bfloat16 l3 = __float2bfloat16(acc.w - __bfloat162float(h3));

    __nv_bfloat162 ph0 = __halves2bfloat162(h0, h1);
    __nv_bfloat162 ph1 = __halves2bfloat162(h2, h3);
    __nv_bfloat162 pl0 = __halves2bfloat162(l0, l1);
    __nv_bfloat162 pl1 = __halves2bfloat162(l2, l3);
    uint2 hv, lv;
    hv.x = *(uint32_t*)&ph0; hv.y = *(uint32_t*)&ph1;
    lv.x = *(uint32_t*)&pl0; lv.y = *(uint32_t*)&pl1;
    ((uint2*)g_hnh)[(size_t)v * 32 + lane] = hv;
    ((uint2*)g_hnl)[(size_t)v * 32 + lane] = lv;
}

// ---------------------------------------------------------------------------
// K5: PERSISTENT GEMM (8 warps, 32x64 warp tile) with SOFTWARE-PIPELINED
// GEMM1 mainloop: ks+1 fragments prefetched into alternate register buffers
// before ks's MMA batch, hiding LDSM latency under MMA execution.
// ---------------------------------------------------------------------------
#define RS 136                              // row stride in bf16
#define RSB (RS * 2)                        // row stride in bytes (272)
#define SM_BIAS  0                          // 192 floats
#define SM_AH    1024
#define SM_AL    (SM_AH  + 128 * RSB)
#define SM_W1H   (SM_AL  + 128 * RSB)
#define SM_W1L   (SM_W1H + 128 * RSB)
#define SM_W2H   (SM_W1L + 128 * RSB)
#define SM_W2L   (SM_W2H + 64 * RSB)
#define SMEM_MM  (SM_W2L + 64 * RSB)        // 175,872 B

#define N_TILES ((N_NODES + 127) / 128)     // 782
#define GEMM_GRID 148

__global__ void __launch_bounds__(256) k_gemm_mma(
    const float* __restrict__ b1, const float* __restrict__ b2,
    float* __restrict__ out, float* __restrict__ emb)
{
    extern __shared__ char smem[];
    const uint32_t sb = smem_u32(smem);
    const int tid  = threadIdx.x;
    const int wid  = tid >> 5;
    const int lane = tid & 31;

    float* sBias = (float*)(smem + SM_BIAS);

    // --- stage bias + weights ONCE ---
    if (tid < F) sBias[tid] = b1[tid];
    else if (tid < F + C) sBias[tid] = b2[tid - F];
    {
        const uint4* w1h4 = (const uint4*)g_w1h;
        const uint4* w1l4 = (const uint4*)g_w1l;
        #pragma unroll
        for (int i = tid; i < 128 * 16; i += 256) {
            int r = i >> 4, c = i & 15;
            *(uint4*)(smem + SM_W1H + r * RSB + c * 16) = w1h4[i];
            *(uint4*)(smem + SM_W1L + r * RSB + c * 16) = w1l4[i];
        }
        const uint4* w2h4 = (const uint4*)g_w2h;
        const uint4* w2l4 = (const uint4*)g_w2l;
        #pragma unroll
        for (int i = tid; i < 64 * 16; i += 256) {
            int r = i >> 4, c = i & 15;
            *(uint4*)(smem + SM_W2H + r * RSB + c * 16) = w2h4[i];
            *(uint4*)(smem + SM_W2L + r * RSB + c * 16) = w2l4[i];
        }
    }

    // ldmatrix per-lane address components
    const int g  = lane >> 3, lr = lane & 7;
    const int a_row = lr + ((g & 1) << 3);
    const int a_kof = (g >> 1) << 3;
    const int b_row = lr + ((g >> 1) << 3);
    const int b_kof = (g & 1) << 3;
    const int wm = wid & 3;                       // M quarter
    const int wn = wid >> 2;                      // N half

    // precomputed per-lane base addresses for GEMM1 fragment loads
    const uint32_t aAH0 = sb + SM_AH + (wm * 32 + a_row) * RSB + a_kof * 2;
    const uint32_t aAH1 = aAH0 + 16 * RSB;
    const uint32_t aAL0 = sb + SM_AL + (wm * 32 + a_row) * RSB + a_kof * 2;
    const uint32_t aAL1 = aAL0 + 16 * RSB;
    const uint32_t aBH  = sb + SM_W1H + (wn * 64 + b_row) * RSB + b_kof * 2;
    const uint32_t aBL  = sb + SM_W1L + (wn * 64 + b_row) * RSB + b_kof * 2;

// load GEMM1 fragments for K-step `ks` into buffer `B`
#define G1_LOAD(B, ks) do {                                                   \
    const uint32_t ko = (uint32_t)(ks) * 32;                                  \
    LDSM4(ahB[B][0][0], ahB[B][0][1], ahB[B][0][2], ahB[B][0][3], aAH0 + ko); \
    LDSM4(ahB[B][1][0], ahB[B][1][1], ahB[B][1][2], ahB[B][1][3], aAH1 + ko); \
    LDSM4(alB[B][0][0], alB[B][0][1], alB[B][0][2], alB[B][0][3], aAL0 + ko); \
    LDSM4(alB[B][1][0], alB[B][1][1], alB[B][1][2], alB[B][1][3], aAL1 + ko); \
    _Pragma("unroll")                                                         \
    for (int nn = 0; nn < 4; nn++) {                                          \
        uint32_t ro = nn * 16 * RSB + ko;                                     \
        LDSM4(bhB[B][2*nn][0], bhB[B][2*nn][1],                               \
              bhB[B][2*nn+1][0], bhB[B][2*nn+1][1], aBH + ro);                \
        LDSM4(blB[B][2*nn][0], blB[B][2*nn][1],                               \
              blB[B][2*nn+1][0], blB[B][2*nn+1][1], aBL + ro);                \
    }                                                                         \
} while (0)

    for (int tile = blockIdx.x; tile < N_TILES; tile += GEMM_GRID) {
        const int node0 = tile * 128;
        __syncthreads();   // previous iteration's smem reads complete

        // --- stage A (hn hi/lo) ---
        #pragma unroll
        for (int i = tid; i < 128 * 16; i += 256) {
            int r = i >> 4, c = i & 15;
            int node = node0 + r;
            uint4 vh = make_uint4(0, 0, 0, 0), vl = make_uint4(0, 0, 0, 0);
            if (node < N_NODES) {
                vh = ((const uint4*)g_hnh)[(size_t)node * 16 + c];
                vl = ((const uint4*)g_hnl)[(size_t)node * 16 + c];
            }
            *(uint4*)(smem + SM_AH + r * RSB + c * 16) = vh;
            *(uint4*)(smem + SM_AL + r * RSB + c * 16) = vl;
        }
        __syncthreads();

        // ================= GEMM1: [128 x 128], pipelined ==================
        float acc[2][8][4];
        #pragma unroll
        for (int m = 0; m < 2; m++)
            #pragma unroll
            for (int n = 0; n < 8; n++)
                #pragma unroll
                for (int q = 0; q < 4; q++) acc[m][n][q] = 0.f;

        uint32_t ahB[2][2][4], alB[2][2][4], bhB[2][8][2], blB[2][8][2];
        G1_LOAD(0, 0);
        #pragma unroll
        for (int ks = 0; ks < 8; ks++) {
            const int cur = ks & 1;
            if (ks < 7) {
                const int nxt = cur ^ 1;
                G1_LOAD(nxt, ks + 1);      // prefetch hides under MMAs below
            }
            #pragma unroll
            for (int m = 0; m < 2; m++)
                #pragma unroll
                for (int n = 0; n < 8; n++) {
                    MMA16816(acc[m][n], ahB[cur][m], bhB[cur][n]);
                    MMA16816(acc[m][n], ahB[cur][m], blB[cur][n]);
                    MMA16816(acc[m][n], alB[cur][m], bhB[cur][n]);
                }
        }
        __syncthreads();   // GEMM1 smem reads done before A overwrite

        // --- epilogue1: +b1, relu -> emb global; bf16 hi/lo into sAh/sAl ---
        {
            const int qr = lane >> 2;
            const int qc = (lane & 3) * 2;
            #pragma unroll
            for (int m = 0; m < 2; m++) {
                #pragma unroll
                for (int n = 0; n < 8; n++) {
                    int col = wn * 64 + n * 8 + qc;
                    float bA = sBias[col], bB = sBias[col + 1];
                    #pragma unroll
                    for (int h = 0; h < 2; h++) {
                        int row = wm * 32 + m * 16 + qr + h * 8;
                        float v0 = fmaxf(acc[m][n][h * 2 + 0] + bA, 0.f);
                        float v1 = fmaxf(acc[m][n][h * 2 + 1] + bB, 0.f);
                        int node = node0 + row;
                        if (node < N_NODES)
                            *(float2*)(emb + (size_t)node * F + col) = make_float2(v0, v1);
                        __nv_bfloat16 h0 = __float2bfloat16(v0);
                        __nv_bfloat16 h1 = __float2bfloat16(v1);
                        __nv_bfloat16 l0 = __float2bfloat16(v0 - __bfloat162float(h0));
                        __nv_bfloat16 l1 = __float2bfloat16(v1 - __bfloat162float(h1));
                        __nv_bfloat162 ph = __halves2bfloat162(h0, h1);
                        __nv_bfloat162 pl = __halves2bfloat162(l0, l1);
                        *(uint32_t*)(smem + SM_AH + row * RSB + col * 2) = *(uint32_t*)&ph;
                        *(uint32_t*)(smem + SM_AL + row * RSB + col * 2) = *(uint32_t*)&pl;
                    }
                }
            }
        }
        __syncthreads();

        // ================= GEMM2: [128 x 64] ==================
        float acc2[2][4][4];
        #pragma unroll
        for (int m = 0; m < 2; m++)
            #pragma unroll
            for (int n = 0; n < 4; n++)
                #pragma unroll
                for (int q = 0; q < 4; q++) acc2[m][n][q] = 0.f;

        #pragma unroll
        for (int ks = 0; ks < 8; ks++) {
            const int k0 = ks * 16;
            uint32_t ah[2][4], al[2][4];
            #pragma unroll
            for (int m = 0; m < 2; m++) {
                int row = wm * 32 + m * 16 + a_row;
                uint32_t off = row * RSB + (k0 + a_kof) * 2;
                LDSM4(ah[m][0], ah[m][1], ah[m][2], ah[m][3], sb + SM_AH + off);
                LDSM4(al[m][0], al[m][1], al[m][2], al[m][3], sb + SM_AL + off);
            }
            uint32_t bh[4][2], bl[4][2];
            #pragma unroll
            for (int nn = 0; nn < 2; nn++) {
                int row = wn * 32 + nn * 16 + b_row;
                uint32_t off = row * RSB + (k0 + b_kof) * 2;
                LDSM4(bh[2*nn][0], bh[2*nn][1], bh[2*nn+1][0], bh[2*nn+1][1],
                      sb + SM_W2H + off);
                LDSM4(bl[2*nn][0], bl[2*nn][1], bl[2*nn+1][0], bl[2*nn+1][1],
                      sb + SM_W2L + off);
            }
            #pragma unroll
            for (int m = 0; m < 2; m++)
                #pragma unroll
                for (int n = 0; n < 4; n++) {
                    MMA16816(acc2[m][n], ah[m], bh[n]);
                    MMA16816(acc2[m][n], ah[m], bl[n]);
                    MMA16816(acc2[m][n], al[m], bh[n]);
                }
        }

        // --- epilogue2: +b2 -> out ---
        {
            const int qr = lane >> 2;
            const int qc = (lane & 3) * 2;
            #pragma unroll
            for (int m = 0; m < 2; m++) {
                #pragma unroll
                for (int n = 0; n < 4; n++) {
                    int col = wn * 32 + n * 8 + qc;
                    float bA = sBias[F + col], bB = sBias[F + col + 1];
                    #pragma unroll
                    for (int h = 0; h < 2; h++) {
                        int row = wm * 32 + m * 16 + qr + h * 8;
                        int node = node0 + row;
                        if (node < N_NODES) {
                            float v0 = acc2[m][n][h * 2 + 0] + bA;
                            float v1 = acc2[m][n][h * 2 + 1] + bB;
                            *(float2*)(out + (size_t)node * C + col) = make_float2(v0, v1);
                        }
                    }
                }
            }
        }
    }
#undef G1_LOAD
}

// ---------------------------------------------------------------------------
extern "C" void kernel_launch(void* const* d_in, const int* in_sizes, int n_in,
                              void* d_out, int out_size) {
    const float* x   = (const float*)d_in[0];
    const int*   src = (const int*)d_in[1];
    const int*   dst = (const int*)d_in[2];
    const float* W1  = (const float*)d_in[3];
    const float* b1  = (const float*)d_in[4];
    const float* W2  = (const float*)d_in[5];
    const float* b2  = (const float*)d_in[6];

    float* out = (float*)d_out;                       // [N_NODES, 64]
    float* emb = out + (size_t)N_NODES * C;           // [N_NODES, 128]

    // prep: zero counters + weight split
    k_prep<<<(N_NODES + 255) / 256, 256>>>(W1, W2);
    // CSR build (unordered segments)
    k_hist<<<(N_EDGES / 2 + 255) / 256, 256>>>(dst);
    k_alloc<<<(N_NODES + 255) / 256, 256>>>();
    k_fill<<<(N_EDGES / 2 + 255) / 256, 256>>>(src, dst);
    // gather-sum + normalize + bf16 split
    k_gather<<<(N_NODES * 32 + 255) / 256, 256>>>(x);
    // persistent GEMMs: software-pipelined GEMM1 mainloop
    cudaFuncSetAttribute(k_gemm_mma, cudaFuncAttributeMaxDynamicSharedMemorySize,
                         SMEM_MM);
    k_gemm_mma<<<GEMM_GRID, 256, SMEM_MM>>>(b1, b2, out, emb);
}